// round 8
// baseline (speedup 1.0000x reference)
#include <cuda_runtime.h>
#include <math.h>

typedef unsigned long long ull;
typedef unsigned int uint;

#define NB 2
#define MTOT 4768
#define SC_CLAMP 4.135166556742356f
#define NEG_S -10000.0f
#define KI 8

// ----------------- static scratch -----------------
__device__ float  g_wt[2304 * 256];                  // [k = ic*9+tap][oc]
__device__ float  g_t[(size_t)NB * 256 * 65536];     // relu(conv), reused per level
__device__ float  g_scores[NB * 196608];
__device__ float  g_deltas[(size_t)NB * 196608 * 4];
__device__ ull    g_keys[(size_t)NB * 196608];
__device__ ull    g_thresh[NB];
__device__ int    g_cnt[NB];
__device__ ull    g_sel[NB * 1024];
__device__ float  g_cscore[NB * MTOT];
__device__ float4 g_cbox[NB * MTOT];
__device__ float4 g_cobox[NB * MTOT];
__device__ int    g_cvalid[NB * MTOT];
__device__ ull    g_gkey[NB * MTOT];
__device__ int    g_order[NB * MTOT];
__device__ ull    g_mask[(size_t)NB * 5 * 1000 * 16];
__device__ int    g_keep[NB * MTOT];

__device__ __forceinline__ uint f2ord(float s) {
    uint u = __float_as_uint(s);
    return (u & 0x80000000u) ? ~u : (u | 0x80000000u);
}
__device__ __forceinline__ float ord2f(uint o) {
    uint u = (o & 0x80000000u) ? (o & 0x7FFFFFFFu) : ~o;
    return __uint_as_float(u);
}

// ----------------- weight transpose: w[oc][ic][tap] -> g_wt[ic*9+tap][oc] -----------------
__global__ void k_transpose_w(const float* __restrict__ w) {
    int idx = blockIdx.x * 256 + threadIdx.x;
    if (idx >= 2304 * 256) return;
    int oc = idx & 255;
    int k = idx >> 8;
    int ic = k / 9, tap = k - ic * 9;
    g_wt[idx] = w[(oc * 256 + ic) * 9 + tap];
}

// ----------------- fused 3x3 conv + bias + relu (canonical im2col k-order) -----------------
__global__ __launch_bounds__(256, 2)
void k_conv(const float* __restrict__ x, const float* __restrict__ bias, int S, int logS) {
    const int P = S * S;
    const int n = blockIdx.z;
    const int ocBase = blockIdx.y * 128;
    const int p0 = blockIdx.x * 128;
    const float* xin = x + (size_t)n * 256 * P;

    __shared__ __align__(16) float sA[KI][128];
    __shared__ __align__(16) float sB[KI][128];

    const int tid = threadIdx.x;
    const int lane = tid & 31;
    const int rowk = tid >> 5;
    const int t_oc = tid >> 4;
    const int t_px = tid & 15;

    int yb[4], xb[4];
#pragma unroll
    for (int j = 0; j < 4; j++) {
        int pb = p0 + lane + 32 * j;
        yb[j] = pb >> logS;
        xb[j] = pb & (S - 1);
    }

    float acc[8][8];
#pragma unroll
    for (int i = 0; i < 8; i++)
#pragma unroll
        for (int j = 0; j < 8; j++) acc[i][j] = 0.f;

    for (int kb = 0; kb < 2304; kb += KI) {
        // this thread's k-row within the chunk: strictly ascending k across the loop
        const int k = kb + rowk;
        const int ic = k / 9;
        const int tap = k - ic * 9;
        const int t3 = tap / 3;
        const int dy = t3 - 1, dx = tap - t3 * 3 - 1;

        *(float4*)&sA[rowk][lane * 4] =
            *(const float4*)(g_wt + (size_t)k * 256 + ocBase + lane * 4);
        const float* xch = xin + (size_t)ic * P;
#pragma unroll
        for (int j = 0; j < 4; j++) {
            int yy = yb[j] + dy, xx = xb[j] + dx;
            float v = 0.f;
            if ((uint)yy < (uint)S && (uint)xx < (uint)S) v = xch[yy * S + xx];
            sB[rowk][lane + 32 * j] = v;
        }
        __syncthreads();
#pragma unroll
        for (int kk = 0; kk < KI; kk++) {
            float a[8], bb[8];
            *(float4*)&a[0] = *(const float4*)&sA[kk][t_oc * 8];
            *(float4*)&a[4] = *(const float4*)&sA[kk][t_oc * 8 + 4];
            *(float4*)&bb[0] = *(const float4*)&sB[kk][t_px * 8];
            *(float4*)&bb[4] = *(const float4*)&sB[kk][t_px * 8 + 4];
#pragma unroll
            for (int i = 0; i < 8; i++)
#pragma unroll
                for (int j = 0; j < 8; j++) acc[i][j] += a[i] * bb[j];
        }
        __syncthreads();
    }

    float* tb = g_t + (size_t)n * 256 * P;
#pragma unroll
    for (int i = 0; i < 8; i++) {
        int oc = ocBase + t_oc * 8 + i;
        float bs = bias[oc];
        float4 v0, v1;
        v0.x = fmaxf(__fadd_rn(acc[i][0], bs), 0.f);
        v0.y = fmaxf(__fadd_rn(acc[i][1], bs), 0.f);
        v0.z = fmaxf(__fadd_rn(acc[i][2], bs), 0.f);
        v0.w = fmaxf(__fadd_rn(acc[i][3], bs), 0.f);
        v1.x = fmaxf(__fadd_rn(acc[i][4], bs), 0.f);
        v1.y = fmaxf(__fadd_rn(acc[i][5], bs), 0.f);
        v1.z = fmaxf(__fadd_rn(acc[i][6], bs), 0.f);
        v1.w = fmaxf(__fadd_rn(acc[i][7], bs), 0.f);
        float* dst = tb + (size_t)oc * P + p0 + t_px * 8;
        *(float4*)dst = v0;
        *(float4*)(dst + 4) = v1;
    }
}

// ----------------- 1x1 heads (sequential ascending ic, single accumulator) -----------------
__global__ void k_head(const float* __restrict__ wobj, const float* __restrict__ bobj,
                       const float* __restrict__ wdel, const float* __restrict__ bdel,
                       int P, int L) {
    __shared__ float w15[15 * 256];
    __shared__ float b15[15];
    int tid = threadIdx.x;
    for (int i = tid; i < 3 * 256; i += 256) w15[i] = wobj[i];
    for (int i = tid; i < 12 * 256; i += 256) w15[3 * 256 + i] = wdel[i];
    if (tid < 3) b15[tid] = bobj[tid];
    else if (tid < 15) b15[tid] = bdel[tid - 3];
    __syncthreads();

    int n = blockIdx.z;
    int p0 = blockIdx.x * 1024 + tid;
    const float* tb = g_t + (size_t)n * 256 * P;
    float acc[15][4];
#pragma unroll
    for (int c = 0; c < 15; c++)
#pragma unroll
        for (int j = 0; j < 4; j++) acc[c][j] = 0.f;

    for (int ic = 0; ic < 256; ic++) {
        float v[4];
#pragma unroll
        for (int j = 0; j < 4; j++) {
            int p = p0 + j * 256;
            v[j] = (p < P) ? tb[(size_t)ic * P + p] : 0.f;
        }
#pragma unroll
        for (int c = 0; c < 15; c++) {
            float ww = w15[c * 256 + ic];
#pragma unroll
            for (int j = 0; j < 4; j++) acc[c][j] += ww * v[j];
        }
    }
#pragma unroll
    for (int j = 0; j < 4; j++) {
        int p = p0 + j * 256;
        if (p >= P) continue;
        size_t base = (size_t)n * L + (size_t)p * 3;
#pragma unroll
        for (int a = 0; a < 3; a++) {
            g_scores[base + a] = __fadd_rn(acc[a][j], b15[a]);
#pragma unroll
            for (int c = 0; c < 4; c++)
                g_deltas[(base + a) * 4 + c] = __fadd_rn(acc[3 + a * 4 + c][j], b15[3 + a * 4 + c]);
        }
    }
}

// ----------------- keys: (ord(score)<<32) | ~idx  (desc order == stable top_k) -----------------
__global__ void k_makekeys(int L) {
    int id = blockIdx.x * 256 + threadIdx.x;
    if (id >= NB * L) return;
    int n = id / L, i = id - n * L;
    float s = g_scores[(size_t)n * L + i];
    g_keys[(size_t)n * L + i] = ((ull)f2ord(s) << 32) | (uint)(~(uint)i);
}

// ----------------- radix-select exact k-th largest key -----------------
__global__ void k_select(int L, int k) {
    __shared__ int hist[256];
    __shared__ ull sprefix;
    __shared__ int sr;
    int b = blockIdx.x;
    int tid = threadIdx.x;
    ull prefix = 0;
    int r = k;
    const ull* keys = g_keys + (size_t)b * L;
    for (int pass = 0; pass < 8; pass++) {
        if (tid < 256) hist[tid] = 0;
        __syncthreads();
        int bsh = 56 - 8 * pass;
        for (int i = tid; i < L; i += 1024) {
            ull key = keys[i];
            bool m = (pass == 0) || ((key >> (64 - 8 * pass)) == prefix);
            if (m) atomicAdd(&hist[(int)((key >> bsh) & 255)], 1);
        }
        __syncthreads();
        if (tid == 0) {
            int acc = 0, byte = 0;
            for (int v = 255; v >= 0; v--) {
                if (acc + hist[v] >= r) { byte = v; break; }
                acc += hist[v];
            }
            sprefix = (prefix << 8) | (uint)byte;
            sr = r - acc;
        }
        __syncthreads();
        prefix = sprefix;
        r = sr;
        __syncthreads();
    }
    if (tid == 0) { g_thresh[b] = prefix; g_cnt[b] = 0; }
}

// ----------------- compact top-k -----------------
__global__ void k_compact(int L) {
    int id = blockIdx.x * 256 + threadIdx.x;
    if (id >= NB * L) return;
    int n = id / L, i = id - n * L;
    ull key = g_keys[(size_t)n * L + i];
    if (key >= g_thresh[n]) {
        int pos = atomicAdd(&g_cnt[n], 1);
        g_sel[n * 1024 + pos] = key;
    }
}

// ----------------- bitonic sort (desc) + decode (unfused _rn arithmetic) -----------------
__global__ void k_sortdecode(int W, int logW, int stride, float size,
                             int lvl, int k, int off, int L) {
    __shared__ ull skey[1024];
    int b = blockIdx.x;
    int tid = threadIdx.x;
    skey[tid] = (tid < k) ? g_sel[b * 1024 + tid] : 0ull;
    __syncthreads();
    for (int len = 2; len <= 1024; len <<= 1)
        for (int j = len >> 1; j > 0; j >>= 1) {
            int ixj = tid ^ j;
            if (ixj > tid) {
                bool desc = ((tid & len) == 0);
                ull a = skey[tid], c = skey[ixj];
                bool sw = desc ? (a < c) : (a > c);
                if (sw) { skey[tid] = c; skey[ixj] = a; }
            }
            __syncthreads();
        }
    if (tid < k) {
        ull key = skey[tid];
        uint idx = ~(uint)key;
        float s = ord2f((uint)(key >> 32));
        int a = idx % 3;
        int cell = idx / 3;
        int hy = cell >> logW, wx = cell & (W - 1);
        float ratio = (a == 0) ? 0.5f : (a == 1) ? 1.0f : 2.0f;
        float ws = __fdiv_rn(size, __fsqrt_rn(ratio));
        float hs = __fmul_rn(ws, ratio);
        float hws = __fmul_rn(0.5f, ws), hhs = __fmul_rn(0.5f, hs);
        float shx = (float)(wx * stride), shy = (float)(hy * stride);
        float ax1 = __fadd_rn(shx, -hws), ay1 = __fadd_rn(shy, -hhs);
        float ax2 = __fadd_rn(shx, hws),  ay2 = __fadd_rn(shy, hhs);
        const float* d = g_deltas + ((size_t)b * L + idx) * 4;
        float dxv = d[0], dyv = d[1];
        float dw = fminf(d[2], SC_CLAMP), dh = fminf(d[3], SC_CLAMP);
        float aw = __fsub_rn(ax2, ax1), ah = __fsub_rn(ay2, ay1);
        float cx = __fadd_rn(ax1, __fmul_rn(0.5f, aw));
        float cy = __fadd_rn(ay1, __fmul_rn(0.5f, ah));
        float pcx = __fadd_rn(__fmul_rn(dxv, aw), cx);
        float pcy = __fadd_rn(__fmul_rn(dyv, ah), cy);
        float ew = (float)exp((double)dw);
        float eh = (float)exp((double)dh);
        float pw = __fmul_rn(ew, aw), ph = __fmul_rn(eh, ah);
        float hpw = __fmul_rn(0.5f, pw), hph = __fmul_rn(0.5f, ph);
        float x1 = __fsub_rn(pcx, hpw), y1 = __fsub_rn(pcy, hph);
        float x2 = __fadd_rn(pcx, hpw), y2 = __fadd_rn(pcy, hph);
        x1 = fminf(fmaxf(x1, 0.f), 1024.f);
        y1 = fminf(fmaxf(y1, 0.f), 1024.f);
        x2 = fminf(fmaxf(x2, 0.f), 1024.f);
        y2 = fminf(fmaxf(y2, 0.f), 1024.f);
        int valid = (__fsub_rn(x2, x1) > 0.f) && (__fsub_rn(y2, y1) > 0.f);
        int ci = off + tid;
        float lo = (float)lvl * 4096.0f;
        g_cscore[b * MTOT + ci] = s;
        g_cbox[b * MTOT + ci] = make_float4(x1, y1, x2, y2);
        g_cobox[b * MTOT + ci] = make_float4(__fadd_rn(x1, lo), __fadd_rn(y1, lo),
                                             __fadd_rn(x2, lo), __fadd_rn(y2, lo));
        g_cvalid[b * MTOT + ci] = valid;
        g_gkey[b * MTOT + ci] = ((ull)(uint)(key >> 32) << 32) | (uint)(~(uint)ci);
    }
}

// ----------------- global rank via merge of 5 sorted lists -----------------
__global__ void k_rank() {
    int b = blockIdx.y;
    int ci = blockIdx.x * 256 + threadIdx.x;
    if (ci >= MTOT) return;
    const int off[6] = {0, 1000, 2000, 3000, 4000, MTOT};
    ull key = g_gkey[b * MTOT + ci];
    int l = ci / 1000; if (l > 4) l = 4;
    int rank = ci - off[l];
    for (int o = 0; o < 5; o++) {
        if (o == l) continue;
        int lo = off[o], hi = off[o + 1];
        while (lo < hi) {
            int mid = (lo + hi) >> 1;
            if (g_gkey[b * MTOT + mid] > key) lo = mid + 1; else hi = mid;
        }
        rank += lo - off[o];
    }
    g_order[b * MTOT + rank] = ci;
}

// ----------------- NMS suppression bitmasks (unfused _rn IoU) -----------------
__global__ void k_mask() {
    int b = blockIdx.z;
    int l = blockIdx.y;
    int k = (l == 4) ? 768 : 1000;
    int i = blockIdx.x * 8 + threadIdx.y;
    int w = threadIdx.x;
    if (i >= k) return;
    int off = l * 1000;
    float4 A = g_cobox[b * MTOT + off + i];
    float areaA = __fmul_rn(__fsub_rn(A.z, A.x), __fsub_rn(A.w, A.y));
    ull word = 0;
    int jmax = i - w * 64; if (jmax > 64) jmax = 64;
    for (int t = 0; t < jmax; t++) {
        int j = w * 64 + t;
        float4 B = g_cobox[b * MTOT + off + j];
        float areaB = __fmul_rn(__fsub_rn(B.z, B.x), __fsub_rn(B.w, B.y));
        float ltx = fmaxf(A.x, B.x), lty = fmaxf(A.y, B.y);
        float rbx = fminf(A.z, B.z), rby = fminf(A.w, B.w);
        float iw = fmaxf(__fsub_rn(rbx, ltx), 0.f);
        float ih = fmaxf(__fsub_rn(rby, lty), 0.f);
        float inter = __fmul_rn(iw, ih);
        float denom = __fadd_rn(__fsub_rn(__fadd_rn(areaA, areaB), inter), 1e-9f);
        float iou = __fdiv_rn(inter, denom);
        if (iou > 0.7f) word |= 1ull << t;
    }
    g_mask[((size_t)(b * 5 + l) * 1000 + i) * 16 + w] = word;
}

// ----------------- serial greedy NMS scan (1 warp per batch-level) -----------------
__global__ void k_nms() {
    int b = blockIdx.y, l = blockIdx.x;
    int k = (l == 4) ? 768 : 1000;
    int off = l * 1000;
    int lane = threadIdx.x;
    const ull* mbase = g_mask + (size_t)(b * 5 + l) * 1000 * 16;
    ull keepw = 0;
    ull row = (lane < 16) ? mbase[lane] : 0;
    for (int i = 0; i < k; i++) {
        ull nrow = (lane < 16 && i + 1 < k) ? mbase[(size_t)(i + 1) * 16 + lane] : 0;
        bool sup = __any_sync(0xFFFFFFFFu, (row & keepw) != 0);
        int vi = g_cvalid[b * MTOT + off + i];
        int ki = (vi && !sup) ? 1 : 0;
        if (ki && lane == (i >> 6)) keepw |= 1ull << (i & 63);
        if (lane == 0) g_keep[b * MTOT + off + i] = ki;
        row = nrow;
    }
}

// ----------------- stable partition + output -----------------
__global__ void k_out(float* __restrict__ out) {
    __shared__ int flag[MTOT];
    __shared__ int part[1024];
    __shared__ int sK;
    int b = blockIdx.x;
    int tid = threadIdx.x;
    for (int r = tid; r < MTOT; r += 1024)
        flag[r] = g_keep[b * MTOT + g_order[b * MTOT + r]];
    __syncthreads();
    int base = tid * 5;
    int mysum = 0;
#pragma unroll
    for (int j = 0; j < 5; j++) {
        int r = base + j;
        if (r < MTOT) mysum += flag[r];
    }
    part[tid] = mysum;
    __syncthreads();
    for (int d = 1; d < 1024; d <<= 1) {
        int v = (tid >= d) ? part[tid - d] : 0;
        __syncthreads();
        part[tid] += v;
        __syncthreads();
    }
    if (tid == 1023) sK = part[1023];
    __syncthreads();
    int run = part[tid] - mysum;
    int Ktot = sK;
    for (int j = 0; j < 5; j++) {
        int r = base + j;
        if (r >= MTOT) break;
        int ci = g_order[b * MTOT + r];
        int f = flag[r];
        int pos;
        float sc;
        if (f) { pos = run; sc = g_cscore[b * MTOT + ci]; }
        else   { pos = Ktot + (r - run); sc = NEG_S; }
        run += f;
        if (pos < 1000) {
            float4 bx = g_cbox[b * MTOT + ci];
            float* o = out + ((size_t)b * 1000 + pos) * 5;
            o[0] = bx.x; o[1] = bx.y; o[2] = bx.z; o[3] = bx.w; o[4] = sc;
        }
    }
}

// ----------------- launch -----------------
extern "C" void kernel_launch(void* const* d_in, const int* in_sizes, int n_in,
                              void* d_out, int out_size) {
    const float* feats[5] = {(const float*)d_in[0], (const float*)d_in[1],
                             (const float*)d_in[2], (const float*)d_in[3],
                             (const float*)d_in[4]};
    const float* w_conv  = (const float*)d_in[5];
    const float* b_conv  = (const float*)d_in[6];
    const float* w_obj   = (const float*)d_in[7];
    const float* b_obj   = (const float*)d_in[8];
    const float* w_delta = (const float*)d_in[9];
    const float* b_delta = (const float*)d_in[10];
    float* out = (float*)d_out;

    const int   Ss[5]  = {256, 128, 64, 32, 16};
    const int   LG[5]  = {8, 7, 6, 5, 4};
    const int   STm[5] = {4, 8, 16, 32, 64};
    const float SZ[5]  = {32.f, 64.f, 128.f, 256.f, 512.f};
    const int   KL[5]  = {1000, 1000, 1000, 1000, 768};
    const int   OFF[5] = {0, 1000, 2000, 3000, 4000};

    k_transpose_w<<<2304, 256>>>(w_conv);

    for (int l = 0; l < 5; l++) {
        int S = Ss[l], P = S * S, L = P * 3;
        k_conv<<<dim3(P / 128, 2, NB), 256>>>(feats[l], b_conv, S, LG[l]);
        k_head<<<dim3((P + 1023) / 1024, 1, NB), 256>>>(w_obj, b_obj, w_delta, b_delta, P, L);
        k_makekeys<<<(NB * L + 255) / 256, 256>>>(L);
        k_select<<<NB, 1024>>>(L, KL[l]);
        k_compact<<<(NB * L + 255) / 256, 256>>>(L);
        k_sortdecode<<<NB, 1024>>>(S, LG[l], STm[l], SZ[l], l, KL[l], OFF[l], L);
    }

    k_rank<<<dim3((MTOT + 255) / 256, NB), 256>>>();
    k_mask<<<dim3(125, 5, NB), dim3(16, 8)>>>();
    k_nms<<<dim3(5, NB), 32>>>();
    k_out<<<NB, 1024>>>(out);
}

// round 9
// speedup vs baseline: 1.0277x; 1.0277x over previous
#include <cuda_runtime.h>
#include <math.h>

typedef unsigned long long ull;
typedef unsigned int uint;

#define NB 2
#define MTOT 4768
#define SC_CLAMP 4.135166556742356f
#define NEG_S -10000.0f
#define KI 8

// ----------------- static scratch -----------------
__device__ float  g_wt[2304 * 256];                  // [k = ic*9+tap][oc]
__device__ float  g_t[(size_t)NB * 256 * 65536];     // relu(conv), reused per level
__device__ float  g_scores[NB * 196608];
__device__ float  g_deltas[(size_t)NB * 196608 * 4];
__device__ ull    g_keys[(size_t)NB * 196608];
__device__ ull    g_thresh[NB];
__device__ int    g_cnt[NB];
__device__ ull    g_sel[NB * 1024];
__device__ float  g_cscore[NB * MTOT];
__device__ float4 g_cbox[NB * MTOT];
__device__ float4 g_cobox[NB * MTOT];
__device__ int    g_cvalid[NB * MTOT];
__device__ ull    g_gkey[NB * MTOT];
__device__ int    g_order[NB * MTOT];
__device__ ull    g_mask[(size_t)NB * 5 * 1000 * 16];
__device__ int    g_keep[NB * MTOT];

__device__ __forceinline__ uint f2ord(float s) {
    uint u = __float_as_uint(s);
    return (u & 0x80000000u) ? ~u : (u | 0x80000000u);
}
__device__ __forceinline__ float ord2f(uint o) {
    uint u = (o & 0x80000000u) ? (o & 0x7FFFFFFFu) : ~o;
    return __uint_as_float(u);
}

// ----------------- weight transpose: w[oc][ic][tap] -> g_wt[ic*9+tap][oc] -----------------
__global__ void k_transpose_w(const float* __restrict__ w) {
    int idx = blockIdx.x * 256 + threadIdx.x;
    if (idx >= 2304 * 256) return;
    int oc = idx & 255;
    int k = idx >> 8;
    int ic = k / 9, tap = k - ic * 9;
    g_wt[idx] = w[(oc * 256 + ic) * 9 + tap];
}

// ----------------- fused 3x3 conv + bias + relu (im2col k-order, packed f32x2 FFMA) -----------------
__global__ __launch_bounds__(256, 2)
void k_conv(const float* __restrict__ x, const float* __restrict__ bias, int S, int logS) {
    const int P = S * S;
    const int n = blockIdx.z;
    const int ocBase = blockIdx.y * 128;
    const int p0 = blockIdx.x * 128;
    const float* xin = x + (size_t)n * 256 * P;

    __shared__ __align__(16) float sA[KI][128];
    __shared__ __align__(16) float sB[KI][128];

    const int tid = threadIdx.x;
    const int lane = tid & 31;
    const int rowk = tid >> 5;
    const int t_oc = tid >> 4;
    const int t_px = tid & 15;

    int yb[4], xb[4];
#pragma unroll
    for (int j = 0; j < 4; j++) {
        int pb = p0 + lane + 32 * j;
        yb[j] = pb >> logS;
        xb[j] = pb & (S - 1);
    }

    // acc2[ii][j] packs accumulators for oc pair (t_oc*8 + 2ii, +2ii+1), pixel j.
    // Each 32-bit half runs the exact same rn-FMA chain as the scalar version.
    ull acc2[4][8];
#pragma unroll
    for (int ii = 0; ii < 4; ii++)
#pragma unroll
        for (int j = 0; j < 8; j++) acc2[ii][j] = 0ull;

    for (int kb = 0; kb < 2304; kb += KI) {
        const int k = kb + rowk;               // strictly ascending k across the loop
        const int ic = k / 9;
        const int tap = k - ic * 9;
        const int t3 = tap / 3;
        const int dy = t3 - 1, dx = tap - t3 * 3 - 1;

        *(float4*)&sA[rowk][lane * 4] =
            *(const float4*)(g_wt + (size_t)k * 256 + ocBase + lane * 4);
        const float* xch = xin + (size_t)ic * P;
#pragma unroll
        for (int j = 0; j < 4; j++) {
            int yy = yb[j] + dy, xx = xb[j] + dx;
            float v = 0.f;
            if ((uint)yy < (uint)S && (uint)xx < (uint)S) v = xch[yy * S + xx];
            sB[rowk][lane + 32 * j] = v;
        }
        __syncthreads();
#pragma unroll
        for (int kk = 0; kk < KI; kk++) {
            // a pairs: consecutive ocs, directly 64-bit loadable from shared
            ull a2[4];
            const ull* ap = (const ull*)&sA[kk][t_oc * 8];
            a2[0] = ap[0]; a2[1] = ap[1]; a2[2] = ap[2]; a2[3] = ap[3];
            // b values + duplicated pairs
            float bb[8];
            *(float4*)&bb[0] = *(const float4*)&sB[kk][t_px * 8];
            *(float4*)&bb[4] = *(const float4*)&sB[kk][t_px * 8 + 4];
            ull bd[8];
#pragma unroll
            for (int j = 0; j < 8; j++) {
                uint ub = __float_as_uint(bb[j]);
                asm("mov.b64 %0, {%1, %1};" : "=l"(bd[j]) : "r"(ub));
            }
#pragma unroll
            for (int ii = 0; ii < 4; ii++)
#pragma unroll
                for (int j = 0; j < 8; j++)
                    asm("fma.rn.f32x2 %0, %1, %2, %0;"
                        : "+l"(acc2[ii][j]) : "l"(a2[ii]), "l"(bd[j]));
        }
        __syncthreads();
    }

    float* tb = g_t + (size_t)n * 256 * P;
#pragma unroll
    for (int ii = 0; ii < 4; ii++) {
        float v[2][8];
#pragma unroll
        for (int j = 0; j < 8; j++) {
            uint lo, hi;
            asm("mov.b64 {%0, %1}, %2;" : "=r"(lo), "=r"(hi) : "l"(acc2[ii][j]));
            v[0][j] = __uint_as_float(lo);
            v[1][j] = __uint_as_float(hi);
        }
#pragma unroll
        for (int h = 0; h < 2; h++) {
            int oc = ocBase + t_oc * 8 + ii * 2 + h;
            float bs = bias[oc];
            float4 v0, v1;
            v0.x = fmaxf(__fadd_rn(v[h][0], bs), 0.f);
            v0.y = fmaxf(__fadd_rn(v[h][1], bs), 0.f);
            v0.z = fmaxf(__fadd_rn(v[h][2], bs), 0.f);
            v0.w = fmaxf(__fadd_rn(v[h][3], bs), 0.f);
            v1.x = fmaxf(__fadd_rn(v[h][4], bs), 0.f);
            v1.y = fmaxf(__fadd_rn(v[h][5], bs), 0.f);
            v1.z = fmaxf(__fadd_rn(v[h][6], bs), 0.f);
            v1.w = fmaxf(__fadd_rn(v[h][7], bs), 0.f);
            float* dst = tb + (size_t)oc * P + p0 + t_px * 8;
            *(float4*)dst = v0;
            *(float4*)(dst + 4) = v1;
        }
    }
}

// ----------------- 1x1 heads (sequential ascending ic, single accumulator) -----------------
__global__ void k_head(const float* __restrict__ wobj, const float* __restrict__ bobj,
                       const float* __restrict__ wdel, const float* __restrict__ bdel,
                       int P, int L) {
    __shared__ float w15[15 * 256];
    __shared__ float b15[15];
    int tid = threadIdx.x;
    for (int i = tid; i < 3 * 256; i += 256) w15[i] = wobj[i];
    for (int i = tid; i < 12 * 256; i += 256) w15[3 * 256 + i] = wdel[i];
    if (tid < 3) b15[tid] = bobj[tid];
    else if (tid < 15) b15[tid] = bdel[tid - 3];
    __syncthreads();

    int n = blockIdx.z;
    int p0 = blockIdx.x * 1024 + tid;
    const float* tb = g_t + (size_t)n * 256 * P;
    float acc[15][4];
#pragma unroll
    for (int c = 0; c < 15; c++)
#pragma unroll
        for (int j = 0; j < 4; j++) acc[c][j] = 0.f;

    for (int ic = 0; ic < 256; ic++) {
        float v[4];
#pragma unroll
        for (int j = 0; j < 4; j++) {
            int p = p0 + j * 256;
            v[j] = (p < P) ? tb[(size_t)ic * P + p] : 0.f;
        }
#pragma unroll
        for (int c = 0; c < 15; c++) {
            float ww = w15[c * 256 + ic];
#pragma unroll
            for (int j = 0; j < 4; j++) acc[c][j] += ww * v[j];
        }
    }
#pragma unroll
    for (int j = 0; j < 4; j++) {
        int p = p0 + j * 256;
        if (p >= P) continue;
        size_t base = (size_t)n * L + (size_t)p * 3;
#pragma unroll
        for (int a = 0; a < 3; a++) {
            g_scores[base + a] = __fadd_rn(acc[a][j], b15[a]);
#pragma unroll
            for (int c = 0; c < 4; c++)
                g_deltas[(base + a) * 4 + c] = __fadd_rn(acc[3 + a * 4 + c][j], b15[3 + a * 4 + c]);
        }
    }
}

// ----------------- keys: (ord(score)<<32) | ~idx  (desc order == stable top_k) -----------------
__global__ void k_makekeys(int L) {
    int id = blockIdx.x * 256 + threadIdx.x;
    if (id >= NB * L) return;
    int n = id / L, i = id - n * L;
    float s = g_scores[(size_t)n * L + i];
    g_keys[(size_t)n * L + i] = ((ull)f2ord(s) << 32) | (uint)(~(uint)i);
}

// ----------------- radix-select exact k-th largest key -----------------
__global__ void k_select(int L, int k) {
    __shared__ int hist[256];
    __shared__ ull sprefix;
    __shared__ int sr;
    int b = blockIdx.x;
    int tid = threadIdx.x;
    ull prefix = 0;
    int r = k;
    const ull* keys = g_keys + (size_t)b * L;
    for (int pass = 0; pass < 8; pass++) {
        if (tid < 256) hist[tid] = 0;
        __syncthreads();
        int bsh = 56 - 8 * pass;
        for (int i = tid; i < L; i += 1024) {
            ull key = keys[i];
            bool m = (pass == 0) || ((key >> (64 - 8 * pass)) == prefix);
            if (m) atomicAdd(&hist[(int)((key >> bsh) & 255)], 1);
        }
        __syncthreads();
        if (tid == 0) {
            int acc = 0, byte = 0;
            for (int v = 255; v >= 0; v--) {
                if (acc + hist[v] >= r) { byte = v; break; }
                acc += hist[v];
            }
            sprefix = (prefix << 8) | (uint)byte;
            sr = r - acc;
        }
        __syncthreads();
        prefix = sprefix;
        r = sr;
        __syncthreads();
    }
    if (tid == 0) { g_thresh[b] = prefix; g_cnt[b] = 0; }
}

// ----------------- compact top-k -----------------
__global__ void k_compact(int L) {
    int id = blockIdx.x * 256 + threadIdx.x;
    if (id >= NB * L) return;
    int n = id / L, i = id - n * L;
    ull key = g_keys[(size_t)n * L + i];
    if (key >= g_thresh[n]) {
        int pos = atomicAdd(&g_cnt[n], 1);
        g_sel[n * 1024 + pos] = key;
    }
}

// ----------------- bitonic sort (desc) + decode (unfused _rn arithmetic) -----------------
__global__ void k_sortdecode(int W, int logW, int stride, float size,
                             int lvl, int k, int off, int L) {
    __shared__ ull skey[1024];
    int b = blockIdx.x;
    int tid = threadIdx.x;
    skey[tid] = (tid < k) ? g_sel[b * 1024 + tid] : 0ull;
    __syncthreads();
    for (int len = 2; len <= 1024; len <<= 1)
        for (int j = len >> 1; j > 0; j >>= 1) {
            int ixj = tid ^ j;
            if (ixj > tid) {
                bool desc = ((tid & len) == 0);
                ull a = skey[tid], c = skey[ixj];
                bool sw = desc ? (a < c) : (a > c);
                if (sw) { skey[tid] = c; skey[ixj] = a; }
            }
            __syncthreads();
        }
    if (tid < k) {
        ull key = skey[tid];
        uint idx = ~(uint)key;
        float s = ord2f((uint)(key >> 32));
        int a = idx % 3;
        int cell = idx / 3;
        int hy = cell >> logW, wx = cell & (W - 1);
        float ratio = (a == 0) ? 0.5f : (a == 1) ? 1.0f : 2.0f;
        float ws = __fdiv_rn(size, __fsqrt_rn(ratio));
        float hs = __fmul_rn(ws, ratio);
        float hws = __fmul_rn(0.5f, ws), hhs = __fmul_rn(0.5f, hs);
        float shx = (float)(wx * stride), shy = (float)(hy * stride);
        float ax1 = __fadd_rn(shx, -hws), ay1 = __fadd_rn(shy, -hhs);
        float ax2 = __fadd_rn(shx, hws),  ay2 = __fadd_rn(shy, hhs);
        const float* d = g_deltas + ((size_t)b * L + idx) * 4;
        float dxv = d[0], dyv = d[1];
        float dw = fminf(d[2], SC_CLAMP), dh = fminf(d[3], SC_CLAMP);
        float aw = __fsub_rn(ax2, ax1), ah = __fsub_rn(ay2, ay1);
        float cx = __fadd_rn(ax1, __fmul_rn(0.5f, aw));
        float cy = __fadd_rn(ay1, __fmul_rn(0.5f, ah));
        float pcx = __fadd_rn(__fmul_rn(dxv, aw), cx);
        float pcy = __fadd_rn(__fmul_rn(dyv, ah), cy);
        float ew = (float)exp((double)dw);
        float eh = (float)exp((double)dh);
        float pw = __fmul_rn(ew, aw), ph = __fmul_rn(eh, ah);
        float hpw = __fmul_rn(0.5f, pw), hph = __fmul_rn(0.5f, ph);
        float x1 = __fsub_rn(pcx, hpw), y1 = __fsub_rn(pcy, hph);
        float x2 = __fadd_rn(pcx, hpw), y2 = __fadd_rn(pcy, hph);
        x1 = fminf(fmaxf(x1, 0.f), 1024.f);
        y1 = fminf(fmaxf(y1, 0.f), 1024.f);
        x2 = fminf(fmaxf(x2, 0.f), 1024.f);
        y2 = fminf(fmaxf(y2, 0.f), 1024.f);
        int valid = (__fsub_rn(x2, x1) > 0.f) && (__fsub_rn(y2, y1) > 0.f);
        int ci = off + tid;
        float lo = (float)lvl * 4096.0f;
        g_cscore[b * MTOT + ci] = s;
        g_cbox[b * MTOT + ci] = make_float4(x1, y1, x2, y2);
        g_cobox[b * MTOT + ci] = make_float4(__fadd_rn(x1, lo), __fadd_rn(y1, lo),
                                             __fadd_rn(x2, lo), __fadd_rn(y2, lo));
        g_cvalid[b * MTOT + ci] = valid;
        g_gkey[b * MTOT + ci] = ((ull)(uint)(key >> 32) << 32) | (uint)(~(uint)ci);
    }
}

// ----------------- global rank via merge of 5 sorted lists -----------------
__global__ void k_rank() {
    int b = blockIdx.y;
    int ci = blockIdx.x * 256 + threadIdx.x;
    if (ci >= MTOT) return;
    const int off[6] = {0, 1000, 2000, 3000, 4000, MTOT};
    ull key = g_gkey[b * MTOT + ci];
    int l = ci / 1000; if (l > 4) l = 4;
    int rank = ci - off[l];
    for (int o = 0; o < 5; o++) {
        if (o == l) continue;
        int lo = off[o], hi = off[o + 1];
        while (lo < hi) {
            int mid = (lo + hi) >> 1;
            if (g_gkey[b * MTOT + mid] > key) lo = mid + 1; else hi = mid;
        }
        rank += lo - off[o];
    }
    g_order[b * MTOT + rank] = ci;
}

// ----------------- NMS suppression bitmasks (unfused _rn IoU) -----------------
__global__ void k_mask() {
    int b = blockIdx.z;
    int l = blockIdx.y;
    int k = (l == 4) ? 768 : 1000;
    int i = blockIdx.x * 8 + threadIdx.y;
    int w = threadIdx.x;
    if (i >= k) return;
    int off = l * 1000;
    float4 A = g_cobox[b * MTOT + off + i];
    float areaA = __fmul_rn(__fsub_rn(A.z, A.x), __fsub_rn(A.w, A.y));
    ull word = 0;
    int jmax = i - w * 64; if (jmax > 64) jmax = 64;
    for (int t = 0; t < jmax; t++) {
        int j = w * 64 + t;
        float4 B = g_cobox[b * MTOT + off + j];
        float areaB = __fmul_rn(__fsub_rn(B.z, B.x), __fsub_rn(B.w, B.y));
        float ltx = fmaxf(A.x, B.x), lty = fmaxf(A.y, B.y);
        float rbx = fminf(A.z, B.z), rby = fminf(A.w, B.w);
        float iw = fmaxf(__fsub_rn(rbx, ltx), 0.f);
        float ih = fmaxf(__fsub_rn(rby, lty), 0.f);
        float inter = __fmul_rn(iw, ih);
        float denom = __fadd_rn(__fsub_rn(__fadd_rn(areaA, areaB), inter), 1e-9f);
        float iou = __fdiv_rn(inter, denom);
        if (iou > 0.7f) word |= 1ull << t;
    }
    g_mask[((size_t)(b * 5 + l) * 1000 + i) * 16 + w] = word;
}

// ----------------- serial greedy NMS scan (1 warp per batch-level) -----------------
__global__ void k_nms() {
    int b = blockIdx.y, l = blockIdx.x;
    int k = (l == 4) ? 768 : 1000;
    int off = l * 1000;
    int lane = threadIdx.x;
    const ull* mbase = g_mask + (size_t)(b * 5 + l) * 1000 * 16;
    ull keepw = 0;
    ull row = (lane < 16) ? mbase[lane] : 0;
    for (int i = 0; i < k; i++) {
        ull nrow = (lane < 16 && i + 1 < k) ? mbase[(size_t)(i + 1) * 16 + lane] : 0;
        bool sup = __any_sync(0xFFFFFFFFu, (row & keepw) != 0);
        int vi = g_cvalid[b * MTOT + off + i];
        int ki = (vi && !sup) ? 1 : 0;
        if (ki && lane == (i >> 6)) keepw |= 1ull << (i & 63);
        if (lane == 0) g_keep[b * MTOT + off + i] = ki;
        row = nrow;
    }
}

// ----------------- stable partition + output -----------------
__global__ void k_out(float* __restrict__ out) {
    __shared__ int flag[MTOT];
    __shared__ int part[1024];
    __shared__ int sK;
    int b = blockIdx.x;
    int tid = threadIdx.x;
    for (int r = tid; r < MTOT; r += 1024)
        flag[r] = g_keep[b * MTOT + g_order[b * MTOT + r]];
    __syncthreads();
    int base = tid * 5;
    int mysum = 0;
#pragma unroll
    for (int j = 0; j < 5; j++) {
        int r = base + j;
        if (r < MTOT) mysum += flag[r];
    }
    part[tid] = mysum;
    __syncthreads();
    for (int d = 1; d < 1024; d <<= 1) {
        int v = (tid >= d) ? part[tid - d] : 0;
        __syncthreads();
        part[tid] += v;
        __syncthreads();
    }
    if (tid == 1023) sK = part[1023];
    __syncthreads();
    int run = part[tid] - mysum;
    int Ktot = sK;
    for (int j = 0; j < 5; j++) {
        int r = base + j;
        if (r >= MTOT) break;
        int ci = g_order[b * MTOT + r];
        int f = flag[r];
        int pos;
        float sc;
        if (f) { pos = run; sc = g_cscore[b * MTOT + ci]; }
        else   { pos = Ktot + (r - run); sc = NEG_S; }
        run += f;
        if (pos < 1000) {
            float4 bx = g_cbox[b * MTOT + ci];
            float* o = out + ((size_t)b * 1000 + pos) * 5;
            o[0] = bx.x; o[1] = bx.y; o[2] = bx.z; o[3] = bx.w; o[4] = sc;
        }
    }
}

// ----------------- launch -----------------
extern "C" void kernel_launch(void* const* d_in, const int* in_sizes, int n_in,
                              void* d_out, int out_size) {
    const float* feats[5] = {(const float*)d_in[0], (const float*)d_in[1],
                             (const float*)d_in[2], (const float*)d_in[3],
                             (const float*)d_in[4]};
    const float* w_conv  = (const float*)d_in[5];
    const float* b_conv  = (const float*)d_in[6];
    const float* w_obj   = (const float*)d_in[7];
    const float* b_obj   = (const float*)d_in[8];
    const float* w_delta = (const float*)d_in[9];
    const float* b_delta = (const float*)d_in[10];
    float* out = (float*)d_out;

    const int   Ss[5]  = {256, 128, 64, 32, 16};
    const int   LG[5]  = {8, 7, 6, 5, 4};
    const int   STm[5] = {4, 8, 16, 32, 64};
    const float SZ[5]  = {32.f, 64.f, 128.f, 256.f, 512.f};
    const int   KL[5]  = {1000, 1000, 1000, 1000, 768};
    const int   OFF[5] = {0, 1000, 2000, 3000, 4000};

    k_transpose_w<<<2304, 256>>>(w_conv);

    for (int l = 0; l < 5; l++) {
        int S = Ss[l], P = S * S, L = P * 3;
        k_conv<<<dim3(P / 128, 2, NB), 256>>>(feats[l], b_conv, S, LG[l]);
        k_head<<<dim3((P + 1023) / 1024, 1, NB), 256>>>(w_obj, b_obj, w_delta, b_delta, P, L);
        k_makekeys<<<(NB * L + 255) / 256, 256>>>(L);
        k_select<<<NB, 1024>>>(L, KL[l]);
        k_compact<<<(NB * L + 255) / 256, 256>>>(L);
        k_sortdecode<<<NB, 1024>>>(S, LG[l], STm[l], SZ[l], l, KL[l], OFF[l], L);
    }

    k_rank<<<dim3((MTOT + 255) / 256, NB), 256>>>();
    k_mask<<<dim3(125, 5, NB), dim3(16, 8)>>>();
    k_nms<<<dim3(5, NB), 32>>>();
    k_out<<<NB, 1024>>>(out);
}